// round 14
// baseline (speedup 1.0000x reference)
#include <cuda_runtime.h>

#define T_STEPS 240
#define H       25
#define BLK     128
#define WPB     (BLK / 32)

typedef unsigned long long u64;

// ---------------------------------------------------------------------------
// Packed f32x2 helpers (Blackwell)
// ---------------------------------------------------------------------------
__device__ __forceinline__ u64 pack2(float lo, float hi) {
    u64 r;
    asm("mov.b64 %0, {%1, %2};" : "=l"(r) : "f"(lo), "f"(hi));
    return r;
}
__device__ __forceinline__ float unpack_sum(u64 v) {
    float lo, hi;
    asm("mov.b64 {%0, %1}, %2;" : "=f"(lo), "=f"(hi) : "l"(v));
    return lo + hi;
}
#define FFMA2(acc, h, w) \
    asm("fma.rn.f32x2 %0, %1, %2, %0;" : "+l"(acc) : "l"(h), "l"(w))

// ---------------------------------------------------------------------------
// Hardware tanh (single MUFU). Sigmoid gates use PRESCALED weights (x0.5
// folded into W/bias at load): sigmoid(v) = fma(tanh(v_scaled), .5, .5).
// ---------------------------------------------------------------------------
__device__ __forceinline__ float tanh_ap(float x) {
    float y;
    asm("tanh.approx.f32 %0, %1;" : "=f"(y) : "f"(x));
    return y;
}
__device__ __forceinline__ float sig_ps(float v_scaled) {
    return fmaf(tanh_ap(v_scaled), 0.5f, 0.5f);
}

// Packed-k indices 0..12 (k pairs (0,1)..(24,25); k=25 padded to 0)
#define R13(M) M(0) M(1) M(2) M(3) M(4) M(5) M(6) M(7) M(8) M(9) M(10) M(11) M(12)

// Register-resident gates: g (x1) and i (x0.5 prescale). f and o live in smem.
#define DECL_WP(Q) u64 wg##Q, wi##Q;

#define LOAD_WP(Q) {                                                          \
    const int k0 = 2 * (Q), k1 = 2 * (Q) + 1;                                 \
    float a, b;                                                               \
    a = (lv && k0 < H) ? __ldg(&W_hh[(2 * H + jc) * H + k0]) : 0.f;           \
    b = (lv && k1 < H) ? __ldg(&W_hh[(2 * H + jc) * H + k1]) : 0.f;           \
    wg##Q = pack2(a, b);                                                      \
    a = (lv && k0 < H) ? 0.5f * __ldg(&W_hh[(0 * H + jc) * H + k0]) : 0.f;    \
    b = (lv && k1 < H) ? 0.5f * __ldg(&W_hh[(0 * H + jc) * H + k1]) : 0.f;    \
    wi##Q = pack2(a, b);                                                      \
}

// Stage f/o gate weights (x0.5 prescale) into block-shared [pair][lane]
// (weights depend only on lane, not warp/batch -> one copy per block).
#define STAGE_WP(Q) {                                                         \
    const int k0 = 2 * (Q), k1 = 2 * (Q) + 1;                                 \
    float a, b;                                                               \
    a = (lv && k0 < H) ? 0.5f * __ldg(&W_hh[(1 * H + jc) * H + k0]) : 0.f;    \
    b = (lv && k1 < H) ? 0.5f * __ldg(&W_hh[(1 * H + jc) * H + k1]) : 0.f;    \
    sWf[Q][lane] = pack2(a, b);                                               \
    a = (lv && k0 < H) ? 0.5f * __ldg(&W_hh[(3 * H + jc) * H + k0]) : 0.f;    \
    b = (lv && k1 < H) ? 0.5f * __ldg(&W_hh[(3 * H + jc) * H + k1]) : 0.f;    \
    sWo[Q][lane] = pack2(a, b);                                               \
}

// Full 13-pair MAC from register weights (same accumulation order as R13
// -> bitwise-identical results).
#define MACR(acc, W, A0, A1, A2, A3, A4, A5, A6)                              \
    FFMA2(acc, (A0).x, W##0);  FFMA2(acc, (A0).y, W##1);                      \
    FFMA2(acc, (A1).x, W##2);  FFMA2(acc, (A1).y, W##3);                      \
    FFMA2(acc, (A2).x, W##4);  FFMA2(acc, (A2).y, W##5);                      \
    FFMA2(acc, (A3).x, W##6);  FFMA2(acc, (A3).y, W##7);                      \
    FFMA2(acc, (A4).x, W##8);  FFMA2(acc, (A4).y, W##9);                      \
    FFMA2(acc, (A5).x, W##10); FFMA2(acc, (A5).y, W##11);                     \
    FFMA2(acc, (A6),   W##12);

// Dual-batch MAC from shared weights: each weight pair loaded once (1 LDS.64,
// conflict-free contiguous 64-bit pattern) and used for both batches.
#define MACS_PAIR(acc0, acc1, SW, Q, AV, CV) {                                \
    u64 w = SW[Q][lane];                                                      \
    FFMA2(acc0, (AV), w);  FFMA2(acc1, (CV), w); }

#define MACS(acc0, acc1, SW, A0, A1, A2, A3, A4, A5, A6,                      \
                          C0, C1, C2, C3, C4, C5, C6)                         \
    MACS_PAIR(acc0, acc1, SW, 0,  (A0).x, (C0).x)                             \
    MACS_PAIR(acc0, acc1, SW, 1,  (A0).y, (C0).y)                             \
    MACS_PAIR(acc0, acc1, SW, 2,  (A1).x, (C1).x)                             \
    MACS_PAIR(acc0, acc1, SW, 3,  (A1).y, (C1).y)                             \
    MACS_PAIR(acc0, acc1, SW, 4,  (A2).x, (C2).x)                             \
    MACS_PAIR(acc0, acc1, SW, 5,  (A2).y, (C2).y)                             \
    MACS_PAIR(acc0, acc1, SW, 6,  (A3).x, (C3).x)                             \
    MACS_PAIR(acc0, acc1, SW, 7,  (A3).y, (C3).y)                             \
    MACS_PAIR(acc0, acc1, SW, 8,  (A4).x, (C4).x)                             \
    MACS_PAIR(acc0, acc1, SW, 9,  (A4).y, (C4).y)                             \
    MACS_PAIR(acc0, acc1, SW, 10, (A5).x, (C5).x)                             \
    MACS_PAIR(acc0, acc1, SW, 11, (A5).y, (C5).y)                             \
    MACS_PAIR(acc0, acc1, SW, 12, (A6),   (C6))

// One LSTM timestep for both batches. g-first schedule (R13); f/o MACs read
// weights from shared.
#define LSTM_STEP(B0, B1, XV0, XV1) do {                                      \
    if (lane < 28) { (B0)[lane] = h0; (B1)[lane] = h1; }                      \
    __syncwarp();                                                             \
    ulonglong2 A0 = *reinterpret_cast<const ulonglong2*>((B0) + 0);           \
    ulonglong2 A1 = *reinterpret_cast<const ulonglong2*>((B0) + 4);           \
    ulonglong2 A2 = *reinterpret_cast<const ulonglong2*>((B0) + 8);           \
    ulonglong2 A3 = *reinterpret_cast<const ulonglong2*>((B0) + 12);          \
    ulonglong2 A4 = *reinterpret_cast<const ulonglong2*>((B0) + 16);          \
    ulonglong2 A5 = *reinterpret_cast<const ulonglong2*>((B0) + 20);          \
    u64        A6 = *reinterpret_cast<const u64*>((B0) + 24);                 \
    ulonglong2 C0 = *reinterpret_cast<const ulonglong2*>((B1) + 0);           \
    ulonglong2 C1 = *reinterpret_cast<const ulonglong2*>((B1) + 4);           \
    ulonglong2 C2 = *reinterpret_cast<const ulonglong2*>((B1) + 8);           \
    ulonglong2 C3 = *reinterpret_cast<const ulonglong2*>((B1) + 12);          \
    ulonglong2 C4 = *reinterpret_cast<const ulonglong2*>((B1) + 16);          \
    ulonglong2 C5 = *reinterpret_cast<const ulonglong2*>((B1) + 20);          \
    u64        C6 = *reinterpret_cast<const u64*>((B1) + 24);                 \
    /* g-gate first: feeds the longest tail chain */                          \
    u64 ag0 = pack2(fmaf((XV0), wih_g, bias_g), 0.f);                         \
    u64 ag1 = pack2(fmaf((XV1), wih_g, bias_g), 0.f);                         \
    MACR(ag0, wg, A0, A1, A2, A3, A4, A5, A6)                                 \
    MACR(ag1, wg, C0, C1, C2, C3, C4, C5, C6)                                 \
    float gg0 = tanh_ap(unpack_sum(ag0));   /* MUFU in flight ... */          \
    float gg1 = tanh_ap(unpack_sum(ag1));                                     \
    /* ... while i/f/o MACs execute */                                        \
    u64 ai0 = pack2(fmaf((XV0), wih_i, bias_i), 0.f);                         \
    u64 ai1 = pack2(fmaf((XV1), wih_i, bias_i), 0.f);                         \
    MACR(ai0, wi, A0, A1, A2, A3, A4, A5, A6)                                 \
    MACR(ai1, wi, C0, C1, C2, C3, C4, C5, C6)                                 \
    u64 af0 = pack2(fmaf((XV0), wih_f, bias_f), 0.f);                         \
    u64 af1 = pack2(fmaf((XV1), wih_f, bias_f), 0.f);                         \
    MACS(af0, af1, sWf, A0, A1, A2, A3, A4, A5, A6,                           \
                        C0, C1, C2, C3, C4, C5, C6)                           \
    u64 ao0 = pack2(fmaf((XV0), wih_o, bias_o), 0.f);                         \
    u64 ao1 = pack2(fmaf((XV1), wih_o, bias_o), 0.f);                         \
    MACS(ao0, ao1, sWo, A0, A1, A2, A3, A4, A5, A6,                           \
                        C0, C1, C2, C3, C4, C5, C6)                           \
    float ig = sig_ps(unpack_sum(ai0));                                       \
    float fg = sig_ps(unpack_sum(af0));                                       \
    float og = sig_ps(unpack_sum(ao0));                                       \
    c0 = fmaf(fg, c0, ig * gg0);  h0 = og * tanh_ap(c0);                      \
    ig = sig_ps(unpack_sum(ai1));                                             \
    fg = sig_ps(unpack_sum(af1));                                             \
    og = sig_ps(unpack_sum(ao1));                                             \
    c1 = fmaf(fg, c1, ig * gg1);  h1 = og * tanh_ap(c1);                      \
} while (0)

__global__ void __launch_bounds__(BLK, 4) lstm_kernel(
    const float* __restrict__ x,      // [B, T, 1]
    const float* __restrict__ W_ih,   // [4H, 1]
    const float* __restrict__ W_hh,   // [4H, H]
    const float* __restrict__ b_ih,   // [4H]
    const float* __restrict__ b_hh,   // [4H]
    const float* __restrict__ W_fc,   // [2, H]
    const float* __restrict__ b_fc,   // [2]
    float* __restrict__ out,          // [B, 2]
    int B)
{
    // h-broadcast buffers (per warp) + block-shared f/o weights.
    __shared__ __align__(16) float hb[WPB][2][2][28];
    __shared__ u64 sWf[13][32];
    __shared__ u64 sWo[13][32];

    const int lane = threadIdx.x & 31;
    const int wIn  = threadIdx.x >> 5;
    const int warpGlobal = (blockIdx.x * BLK + threadIdx.x) >> 5;

    const bool lv = (lane < H);
    const int  jc = lv ? lane : (H - 1);

    int b0 = 2 * warpGlobal;
    int b1 = 2 * warpGlobal + 1;
    const bool v0 = (b0 < B), v1 = (b1 < B);
    if (!v0) b0 = B - 1;
    if (!v1) b1 = B - 1;

    // Register-resident g/i weights: 26 named u64 SSA values.
    R13(DECL_WP)
    R13(LOAD_WP)

    // f/o weights -> shared (warp 0 lanes own the per-lane mapping).
    if (wIn == 0) { R13(STAGE_WP) }

    // x-projection weights & biases; i/f/o prescaled by 0.5 (exact).
    const float wih_i = lv ? 0.5f * __ldg(&W_ih[0 * H + jc]) : 0.f;
    const float wih_f = lv ? 0.5f * __ldg(&W_ih[1 * H + jc]) : 0.f;
    const float wih_g = lv ?        __ldg(&W_ih[2 * H + jc]) : 0.f;
    const float wih_o = lv ? 0.5f * __ldg(&W_ih[3 * H + jc]) : 0.f;
    const float bias_i = lv ? 0.5f * (__ldg(&b_ih[0 * H + jc]) + __ldg(&b_hh[0 * H + jc])) : 0.f;
    const float bias_f = lv ? 0.5f * (__ldg(&b_ih[1 * H + jc]) + __ldg(&b_hh[1 * H + jc])) : 0.f;
    const float bias_g = lv ?        (__ldg(&b_ih[2 * H + jc]) + __ldg(&b_hh[2 * H + jc])) : 0.f;
    const float bias_o = lv ? 0.5f * (__ldg(&b_ih[3 * H + jc]) + __ldg(&b_hh[3 * H + jc])) : 0.f;

    __syncthreads();   // sWf/sWo visible to all warps

    float* bA0 = &hb[wIn][0][0][0];
    float* bA1 = &hb[wIn][0][1][0];
    float* bB0 = &hb[wIn][1][0][0];
    float* bB1 = &hb[wIn][1][1][0];

    float h0 = 0.f, c0 = 0.f, h1 = 0.f, c1 = 0.f;

    const float4* xq0p = reinterpret_cast<const float4*>(x + (size_t)b0 * T_STEPS);
    const float4* xq1p = reinterpret_cast<const float4*>(x + (size_t)b1 * T_STEPS);

#pragma unroll 1
    for (int t4 = 0; t4 < T_STEPS / 4; t4++) {
        float4 xq0 = __ldg(xq0p + t4);   // warp-uniform broadcast loads
        float4 xq1 = __ldg(xq1p + t4);
        LSTM_STEP(bA0, bA1, xq0.x, xq1.x);
        LSTM_STEP(bB0, bB1, xq0.y, xq1.y);
        LSTM_STEP(bA0, bA1, xq0.z, xq1.z);
        LSTM_STEP(bB0, bB1, xq0.w, xq1.w);
    }

    // FC head: warp-reduce h . W_fc^T (idle lanes contribute h=0)
    const float wfc0 = lv ? __ldg(&W_fc[jc])     : 0.f;
    const float wfc1 = lv ? __ldg(&W_fc[H + jc]) : 0.f;
    float s00 = h0 * wfc0, s01 = h0 * wfc1;
    float s10 = h1 * wfc0, s11 = h1 * wfc1;
#pragma unroll
    for (int off = 16; off > 0; off >>= 1) {
        s00 += __shfl_xor_sync(0xffffffffu, s00, off);
        s01 += __shfl_xor_sync(0xffffffffu, s01, off);
        s10 += __shfl_xor_sync(0xffffffffu, s10, off);
        s11 += __shfl_xor_sync(0xffffffffu, s11, off);
    }
    if (lane == 0) {
        const float bf0 = __ldg(&b_fc[0]), bf1 = __ldg(&b_fc[1]);
        if (v0) {
            out[(size_t)b0 * 2 + 0] = s00 + bf0;
            out[(size_t)b0 * 2 + 1] = s01 + bf1;
        }
        if (v1) {
            out[(size_t)b1 * 2 + 0] = s10 + bf0;
            out[(size_t)b1 * 2 + 1] = s11 + bf1;
        }
    }
}

extern "C" void kernel_launch(void* const* d_in, const int* in_sizes, int n_in,
                              void* d_out, int out_size) {
    const float* x    = (const float*)d_in[0];
    const float* W_ih = (const float*)d_in[1];
    const float* W_hh = (const float*)d_in[2];
    const float* b_ih = (const float*)d_in[3];
    const float* b_hh = (const float*)d_in[4];
    const float* W_fc = (const float*)d_in[5];
    const float* b_fc = (const float*)d_in[6];

    int B = in_sizes[0] / T_STEPS;          // x is [B, T, 1]
    int warpsNeeded = (B + 1) / 2;          // 2 batches per warp
    int blocks      = (warpsNeeded * 32 + BLK - 1) / BLK;

    lstm_kernel<<<blocks, BLK>>>(x, W_ih, W_hh, b_ih, b_hh, W_fc, b_fc,
                                 (float*)d_out, B);
}